// round 1
// baseline (speedup 1.0000x reference)
#include <cuda_runtime.h>

// SpikingVestibular: B=500k independent elements, N=6 neurons, 10 Izhikevich
// steps + 8-substep two-compartment relaxation. Pure HBM-streaming kernel:
// one thread per batch element, everything in registers, float2 vector I/O.

__global__ __launch_bounds__(256)
void sv_kernel(const float* __restrict__ speed_p,
               const float* __restrict__ turn_p,
               const float* __restrict__ pt_p,
               const float* __restrict__ ps_p,
               const float* __restrict__ noise,
               const float* __restrict__ v0,
               const float* __restrict__ u0,
               const float* __restrict__ r0,
               float* __restrict__ out,
               int B)
{
    int b = blockIdx.x * blockDim.x + threadIdx.x;
    if (b >= B) return;

    float speed = speed_p[b];
    float tr    = turn_p[b];

    float tilt = fminf(1.0f, fabsf(tr) * speed * 0.5f);

    float I[6];
    I[0] = fmaxf(0.0f,  tr) * 10.0f;
    I[1] = fmaxf(0.0f, -tr) * 10.0f;
    I[2] = speed * 5.0f;
    I[3] = fmaxf(0.0f, -speed + 0.5f) * 5.0f;
    I[4] = tilt * 8.0f;
    I[5] = tilt * 8.0f;

    size_t base = (size_t)b * 6;

    float v[6], u[6], r[6];
    {
        const float2* v2 = reinterpret_cast<const float2*>(v0 + base);
        const float2* u2 = reinterpret_cast<const float2*>(u0 + base);
        const float2* r2 = reinterpret_cast<const float2*>(r0 + base);
        #pragma unroll
        for (int i = 0; i < 3; i++) {
            float2 a = v2[i]; v[2*i] = a.x; v[2*i+1] = a.y;
            float2 c = u2[i]; u[2*i] = c.x; u[2*i+1] = c.y;
            float2 d = r2[i]; r[2*i] = d.x; r[2*i+1] = d.y;
        }
    }

    size_t stepStride = (size_t)B * 6;

    #pragma unroll
    for (int s = 0; s < 10; s++) {
        float nz[6];
        {
            const float2* nz2 =
                reinterpret_cast<const float2*>(noise + (size_t)s * stepStride + base);
            #pragma unroll
            for (int i = 0; i < 3; i++) {
                float2 a = nz2[i]; nz[2*i] = a.x; nz[2*i+1] = a.y;
            }
        }
        #pragma unroll
        for (int n = 0; n < 6; n++) {
            float i_tot = I[n] + nz[n] * 0.3f - 1.0f;
            float vv = v[n];
            vv = vv + (0.04f * vv * vv + 5.0f * vv + 140.0f - u[n] + i_tot);
            float uu = u[n] + 0.02f * (0.2f * vv - u[n]);
            bool fired = (vv >= 30.0f);
            float spk = fired ? 1.0f : 0.0f;
            if (fired) vv = -65.0f;
            uu += spk * 8.0f;
            r[n] = r[n] * 0.9f + spk * 0.1f;
            v[n] = vv;
            u[n] = uu;
        }
    }

    float rate_mean = (r[0] + r[1] + r[2] + r[3] + r[4] + r[5]) * (1.0f / 6.0f);

    // Two-compartment column: iterate 8 substeps (cheap, matches ref rounding).
    float pt = pt_p[b];
    float ps = ps_p[b];
    float vb0 = 0.0f, vb1 = 0.0f, va0 = 0.0f, va1 = 0.0f;
    #pragma unroll
    for (int s = 0; s < 8; s++) {
        vb0 += 0.5f * (tr    - vb0);
        vb1 += 0.5f * (speed - vb1);
        va0 += 0.5f * (pt    - va0);
        va1 += 0.5f * (ps    - va1);
    }
    float pe0 = vb0 - va0;
    float pe1 = vb1 - va1;
    float p0 = 1.0f / (1.0f + pe0 * pe0);
    float p1 = 1.0f / (1.0f + pe1 * pe1);
    float fe = 0.5f * (p0 * pe0 * pe0 + p1 * pe1 * pe1);
    float pe_w = 0.7f * pe0 + 0.3f * pe1;
    float prec_mean = 0.5f * (p0 + p1);
    float postural = -prec_mean * pe_w * 0.3f;

    float2* o2 = reinterpret_cast<float2*>(out + base);
    o2[0] = make_float2(tilt, rate_mean);
    o2[1] = make_float2(postural, pe_w);
    o2[2] = make_float2(prec_mean, fe);
}

extern "C" void kernel_launch(void* const* d_in, const int* in_sizes, int n_in,
                              void* d_out, int out_size) {
    // metadata order: heading, speed, turn_rate, predicted_turn,
    //                 predicted_speed, noise, v0, u0, rate0
    const float* speed = (const float*)d_in[1];
    const float* turn  = (const float*)d_in[2];
    const float* pt    = (const float*)d_in[3];
    const float* ps    = (const float*)d_in[4];
    const float* noise = (const float*)d_in[5];
    const float* v0    = (const float*)d_in[6];
    const float* u0    = (const float*)d_in[7];
    const float* r0    = (const float*)d_in[8];

    int B = in_sizes[0];
    int threads = 256;
    int blocks = (B + threads - 1) / threads;
    sv_kernel<<<blocks, threads>>>(speed, turn, pt, ps, noise, v0, u0, r0,
                                   (float*)d_out, B);
}